// round 4
// baseline (speedup 1.0000x reference)
#include <cuda_runtime.h>

#define N_NODES 50000
#define N_EDGES 800000
#define D 96
#define WS 100    // padded stride: 400B rows (16B-aligned)

__device__ __align__(16) float g_agg[N_NODES * D];   // gathered mean features
__device__ __align__(16) float g_h[N_NODES * D];     // layer-1 activations
__device__ int g_deg[N_NODES];
__device__ int g_off[N_NODES + 1];
__device__ int g_cur[N_NODES];
__device__ int g_src[N_EDGES];                        // CSR: src ids grouped by dst
__device__ int g_is64;                                // 1 if edge_index is int64

// ---------------------------------------------------------------------------
// Detect edge_index element width. int64 little-endian small non-negative ids
// have all high words == 0; int32 random ids in [0,50000) do not.
// Deterministic for fixed input.
// ---------------------------------------------------------------------------
__global__ void detect_kernel(const int* __restrict__ w) {
    if (threadIdx.x == 0 && blockIdx.x == 0) {
        int is64 = 1;
        for (int i = 1; i < 128; i += 2)
            if (w[i] != 0) { is64 = 0; break; }
        g_is64 = is64;
    }
}

__device__ __forceinline__ int load_idx(const void* eiv, int pos) {
    int v;
    if (g_is64) v = (int)((const long long*)eiv)[pos];
    else        v = ((const int*)eiv)[pos];
    // clamp: no-op when parsing is correct; prevents OOB traps if not
    return min(max(v, 0), N_NODES - 1);
}

// ---------------------------------------------------------------------------
// CSR build: zero degrees -> histogram -> scan -> place
// ---------------------------------------------------------------------------
__global__ void zero_deg_kernel() {
    int i = blockIdx.x * blockDim.x + threadIdx.x;
    if (i < N_NODES) g_deg[i] = 0;
}

__global__ void hist_kernel(const void* __restrict__ eiv) {
    int e = blockIdx.x * blockDim.x + threadIdx.x;
    if (e < N_EDGES) {
        int dst = load_idx(eiv, N_EDGES + e);
        atomicAdd(&g_deg[dst], 1);
    }
}

__global__ void scan_kernel() {           // single block, 1024 threads
    __shared__ int part[1024];
    const int T = 1024;
    const int C = (N_NODES + T - 1) / T;  // 49
    int t = threadIdx.x;
    int base = t * C;
    int s = 0;
    for (int i = 0; i < C; i++) {
        int idx = base + i;
        if (idx < N_NODES) s += g_deg[idx];
    }
    part[t] = s;
    __syncthreads();
    for (int off = 1; off < T; off <<= 1) {
        int v = (t >= off) ? part[t - off] : 0;
        __syncthreads();
        part[t] += v;
        __syncthreads();
    }
    int excl = part[t] - s;
    for (int i = 0; i < C; i++) {
        int idx = base + i;
        if (idx < N_NODES) {
            g_off[idx] = excl;
            g_cur[idx] = 0;
            excl += g_deg[idx];
        }
    }
    if (t == T - 1) g_off[N_NODES] = excl;
}

__global__ void place_kernel(const void* __restrict__ eiv) {
    int e = blockIdx.x * blockDim.x + threadIdx.x;
    if (e < N_EDGES) {
        int src = load_idx(eiv, e);
        int dst = load_idx(eiv, N_EDGES + e);
        int pos = g_off[dst] + atomicAdd(&g_cur[dst], 1);
        if (pos >= 0 && pos < N_EDGES) g_src[pos] = src;
    }
}

// ---------------------------------------------------------------------------
// Gather mean aggregation: one warp per node, 3 coalesced columns per lane.
// No atomics; writes normalized mean directly (0 for isolated nodes).
// ---------------------------------------------------------------------------
__global__ __launch_bounds__(256) void gather_kernel(const float* __restrict__ x,
                                                     int from_h) {
    int warp = (blockIdx.x * blockDim.x + threadIdx.x) >> 5;
    int lane = threadIdx.x & 31;
    if (warp >= N_NODES) return;
    const float* feat = from_h ? (const float*)g_h : x;
    int beg = g_off[warp];
    int end = g_off[warp + 1];
    float a0 = 0.f, a1 = 0.f, a2 = 0.f;
    int i = beg;
    for (; i + 1 < end; i += 2) {
        int s0 = g_src[i];
        int s1 = g_src[i + 1];
        const float* r0 = feat + (size_t)s0 * D;
        const float* r1 = feat + (size_t)s1 * D;
        float x0 = r0[lane], x1 = r0[lane + 32], x2 = r0[lane + 64];
        float y0 = r1[lane], y1 = r1[lane + 32], y2 = r1[lane + 64];
        a0 += x0 + y0; a1 += x1 + y1; a2 += x2 + y2;
    }
    if (i < end) {
        const float* r = feat + (size_t)g_src[i] * D;
        a0 += r[lane]; a1 += r[lane + 32]; a2 += r[lane + 64];
    }
    float inv = 1.0f / (float)max(end - beg, 1);
    float* o = g_agg + (size_t)warp * D;
    o[lane]      = a0 * inv;
    o[lane + 32] = a1 * inv;
    o[lane + 64] = a2 * inv;
}

// ---------------------------------------------------------------------------
// Fused SAGE linear layer:
//   out[n] = g_agg[n] @ Wl^T + bias + feat[n] @ Wr^T   (optional ELU)
// One thread per node. Single 96x100 static shared weight buffer, restaged
// between the Wl and Wr phases (all reads are warp-uniform -> broadcast).
// ---------------------------------------------------------------------------
__global__ __launch_bounds__(128) void gemm_kernel(
    const float* __restrict__ x, int in_h,
    const float* __restrict__ Wl,
    const float* __restrict__ Wr,
    const float* __restrict__ bias,
    float* __restrict__ out, int out_h,
    int apply_elu)
{
    __shared__ float ws[D * WS];   // ws[k*WS + o] = W[o][k]  (38400 B)
    __shared__ float bsm[D];

    const float* feat = in_h ? (const float*)g_h : x;
    float* dst = out_h ? (float*)g_h : out;

    for (int i = threadIdx.x; i < D * D; i += 128) {
        int o = i / D, k = i % D;
        ws[k * WS + o] = Wl[i];
    }
    if (threadIdx.x < D) bsm[threadIdx.x] = bias[threadIdx.x];
    __syncthreads();

    int node = blockIdx.x * 128 + threadIdx.x;
    bool active = node < N_NODES;

    float acc[D];
#pragma unroll
    for (int j = 0; j < D; j++) acc[j] = bsm[j];

    const float4* a4 = (const float4*)(g_agg + (size_t)node * D);
    const float4* f4 = (const float4*)(feat + (size_t)node * D);

    if (active) {
#pragma unroll 1
        for (int kb = 0; kb < D / 4; kb++) {
            float4 av = a4[kb];
            float a0 = av.x, a1 = av.y, a2 = av.z, a3 = av.w;
            const float4* w0 = (const float4*)(ws + (4 * kb + 0) * WS);
            const float4* w1 = (const float4*)(ws + (4 * kb + 1) * WS);
            const float4* w2 = (const float4*)(ws + (4 * kb + 2) * WS);
            const float4* w3 = (const float4*)(ws + (4 * kb + 3) * WS);
#pragma unroll
            for (int j = 0; j < 24; j++) {
                float4 w = w0[j];
                acc[4 * j]     = fmaf(a0, w.x, acc[4 * j]);
                acc[4 * j + 1] = fmaf(a0, w.y, acc[4 * j + 1]);
                acc[4 * j + 2] = fmaf(a0, w.z, acc[4 * j + 2]);
                acc[4 * j + 3] = fmaf(a0, w.w, acc[4 * j + 3]);
            }
#pragma unroll
            for (int j = 0; j < 24; j++) {
                float4 w = w1[j];
                acc[4 * j]     = fmaf(a1, w.x, acc[4 * j]);
                acc[4 * j + 1] = fmaf(a1, w.y, acc[4 * j + 1]);
                acc[4 * j + 2] = fmaf(a1, w.z, acc[4 * j + 2]);
                acc[4 * j + 3] = fmaf(a1, w.w, acc[4 * j + 3]);
            }
#pragma unroll
            for (int j = 0; j < 24; j++) {
                float4 w = w2[j];
                acc[4 * j]     = fmaf(a2, w.x, acc[4 * j]);
                acc[4 * j + 1] = fmaf(a2, w.y, acc[4 * j + 1]);
                acc[4 * j + 2] = fmaf(a2, w.z, acc[4 * j + 2]);
                acc[4 * j + 3] = fmaf(a2, w.w, acc[4 * j + 3]);
            }
#pragma unroll
            for (int j = 0; j < 24; j++) {
                float4 w = w3[j];
                acc[4 * j]     = fmaf(a3, w.x, acc[4 * j]);
                acc[4 * j + 1] = fmaf(a3, w.y, acc[4 * j + 1]);
                acc[4 * j + 2] = fmaf(a3, w.z, acc[4 * j + 2]);
                acc[4 * j + 3] = fmaf(a3, w.w, acc[4 * j + 3]);
            }
        }
    }

    __syncthreads();
    for (int i = threadIdx.x; i < D * D; i += 128) {
        int o = i / D, k = i % D;
        ws[k * WS + o] = Wr[i];
    }
    __syncthreads();

    if (active) {
#pragma unroll 1
        for (int kb = 0; kb < D / 4; kb++) {
            float4 fv = f4[kb];
            float a0 = fv.x, a1 = fv.y, a2 = fv.z, a3 = fv.w;
            const float4* w0 = (const float4*)(ws + (4 * kb + 0) * WS);
            const float4* w1 = (const float4*)(ws + (4 * kb + 1) * WS);
            const float4* w2 = (const float4*)(ws + (4 * kb + 2) * WS);
            const float4* w3 = (const float4*)(ws + (4 * kb + 3) * WS);
#pragma unroll
            for (int j = 0; j < 24; j++) {
                float4 w = w0[j];
                acc[4 * j]     = fmaf(a0, w.x, acc[4 * j]);
                acc[4 * j + 1] = fmaf(a0, w.y, acc[4 * j + 1]);
                acc[4 * j + 2] = fmaf(a0, w.z, acc[4 * j + 2]);
                acc[4 * j + 3] = fmaf(a0, w.w, acc[4 * j + 3]);
            }
#pragma unroll
            for (int j = 0; j < 24; j++) {
                float4 w = w1[j];
                acc[4 * j]     = fmaf(a1, w.x, acc[4 * j]);
                acc[4 * j + 1] = fmaf(a1, w.y, acc[4 * j + 1]);
                acc[4 * j + 2] = fmaf(a1, w.z, acc[4 * j + 2]);
                acc[4 * j + 3] = fmaf(a1, w.w, acc[4 * j + 3]);
            }
#pragma unroll
            for (int j = 0; j < 24; j++) {
                float4 w = w2[j];
                acc[4 * j]     = fmaf(a2, w.x, acc[4 * j]);
                acc[4 * j + 1] = fmaf(a2, w.y, acc[4 * j + 1]);
                acc[4 * j + 2] = fmaf(a2, w.z, acc[4 * j + 2]);
                acc[4 * j + 3] = fmaf(a2, w.w, acc[4 * j + 3]);
            }
#pragma unroll
            for (int j = 0; j < 24; j++) {
                float4 w = w3[j];
                acc[4 * j]     = fmaf(a3, w.x, acc[4 * j]);
                acc[4 * j + 1] = fmaf(a3, w.y, acc[4 * j + 1]);
                acc[4 * j + 2] = fmaf(a3, w.z, acc[4 * j + 2]);
                acc[4 * j + 3] = fmaf(a3, w.w, acc[4 * j + 3]);
            }
        }

        float* o = dst + (size_t)node * D;
        if (apply_elu) {
#pragma unroll
            for (int j = 0; j < D; j++) {
                float v = acc[j];
                o[j] = v > 0.0f ? v : expm1f(v);
            }
        } else {
#pragma unroll
            for (int j = 0; j < D; j++) o[j] = acc[j];
        }
    }
}

// ---------------------------------------------------------------------------
// Launch sequence (graph-capturable; kernel launches only).
// ---------------------------------------------------------------------------
extern "C" void kernel_launch(void* const* d_in, const int* in_sizes, int n_in,
                              void* d_out, int out_size) {
    const float* x   = (const float*)d_in[0];
    const void*  ei  = d_in[1];
    const float* W1l = (const float*)d_in[2];
    const float* b1  = (const float*)d_in[3];
    const float* W1r = (const float*)d_in[4];
    const float* W2l = (const float*)d_in[5];
    const float* b2  = (const float*)d_in[6];
    const float* W2r = (const float*)d_in[7];
    float*       out = (float*)d_out;

    const int nb = (N_NODES + 255) / 256;
    const int eb = (N_EDGES + 255) / 256;
    const int wb = (N_NODES * 32 + 255) / 256;
    const int gb = (N_NODES + 127) / 128;

    // CSR build (shared by both layers)
    detect_kernel<<<1, 32>>>((const int*)ei);
    zero_deg_kernel<<<nb, 256>>>();
    hist_kernel<<<eb, 256>>>(ei);
    scan_kernel<<<1, 1024>>>();
    place_kernel<<<eb, 256>>>(ei);

    // Layer 1: gather from x, gemm -> g_h (with ELU)
    gather_kernel<<<wb, 256>>>(x, 0);
    gemm_kernel<<<gb, 128>>>(x, 0, W1l, W1r, b1, nullptr, 1, 1);

    // Layer 2: gather from g_h, gemm -> out
    gather_kernel<<<wb, 256>>>(nullptr, 1);
    gemm_kernel<<<gb, 128>>>(nullptr, 1, W2l, W2r, b2, out, 0, 0);
}

// round 5
// speedup vs baseline: 1.3108x; 1.3108x over previous
#include <cuda_runtime.h>

#define N_NODES 50000
#define N_EDGES 800000
#define D 96
#define WS 100                  // padded weight stride: 400B rows, 8B-aligned
#define SCAN_T 1024
#define SCAN_B ((N_NODES + SCAN_T - 1) / SCAN_T)   // 49

typedef unsigned long long u64;

__device__ __align__(16) float g_agg[N_NODES * D];   // gathered mean features
__device__ __align__(16) float g_h[N_NODES * D];     // layer-1 activations
__device__ int g_deg[N_NODES];
__device__ int g_off[N_NODES + 1];
__device__ int g_cur[N_NODES];
__device__ int g_src[N_EDGES];                        // CSR: src ids grouped by dst
__device__ int g_part[SCAN_B];                        // per-block partial sums
__device__ int g_is64;                                // 1 if edge_index is int64

__device__ __forceinline__ u64 pack2(float lo, float hi) {
    u64 r; asm("mov.b64 %0, {%1, %2};" : "=l"(r) : "f"(lo), "f"(hi)); return r;
}
__device__ __forceinline__ void unpack2(u64 v, float& lo, float& hi) {
    asm("mov.b64 {%0, %1}, %2;" : "=f"(lo), "=f"(hi) : "l"(v));
}
__device__ __forceinline__ void fma2(u64& d, u64 a, u64 b) {
    asm("fma.rn.f32x2 %0, %1, %2, %0;" : "+l"(d) : "l"(a), "l"(b));
}

// ---------------------------------------------------------------------------
// Detect edge_index element width (parallel, 64 threads + ballot).
// int64 small non-negative ids => all odd 32-bit words are zero.
// ---------------------------------------------------------------------------
__global__ void detect_kernel(const int* __restrict__ w) {
    int t = threadIdx.x;                    // 64 threads check words 1,3,...,127
    int bad = (w[2 * t + 1] != 0) ? 1 : 0;
    unsigned m0 = __ballot_sync(0xffffffffu, bad);
    __shared__ unsigned s[2];
    s[t >> 5] = m0;
    __syncthreads();
    if (t == 0) g_is64 = (s[0] | s[1]) ? 0 : 1;
}

__device__ __forceinline__ int load_idx(const void* eiv, int pos) {
    int v;
    if (g_is64) v = (int)((const long long*)eiv)[pos];
    else        v = ((const int*)eiv)[pos];
    return min(max(v, 0), N_NODES - 1);     // safety clamp (no-op when correct)
}

// ---------------------------------------------------------------------------
// CSR build
// ---------------------------------------------------------------------------
__global__ void zero_deg_kernel() {
    int i = blockIdx.x * blockDim.x + threadIdx.x;
    if (i < N_NODES) g_deg[i] = 0;
}

__global__ void hist_kernel(const void* __restrict__ eiv) {
    int e = blockIdx.x * blockDim.x + threadIdx.x;
    if (e < N_EDGES) atomicAdd(&g_deg[load_idx(eiv, N_EDGES + e)], 1);
}

// Phase 1: per-block sums of degree chunks
__global__ __launch_bounds__(SCAN_T) void scan1_kernel() {
    __shared__ int wsum[32];
    int i = blockIdx.x * SCAN_T + threadIdx.x;
    int v = (i < N_NODES) ? g_deg[i] : 0;
    int s = v;
#pragma unroll
    for (int o = 1; o < 32; o <<= 1) s += __shfl_xor_sync(0xffffffffu, s, o);
    if ((threadIdx.x & 31) == 0) wsum[threadIdx.x >> 5] = s;
    __syncthreads();
    if (threadIdx.x < 32) {
        int t = wsum[threadIdx.x];
#pragma unroll
        for (int o = 1; o < 32; o <<= 1) t += __shfl_xor_sync(0xffffffffu, t, o);
        if (threadIdx.x == 0) g_part[blockIdx.x] = t;
    }
}

// Phase 2: exclusive scan of the 49 block partials (one warp pass in 64 lanes)
__global__ void scan2_kernel() {
    int t = threadIdx.x;                    // 64 threads
    int v = (t < SCAN_B) ? g_part[t] : 0;
    int s = v;
#pragma unroll
    for (int o = 1; o < 32; o <<= 1) {
        int u = __shfl_up_sync(0xffffffffu, s, o);
        if ((t & 31) >= o) s += u;
    }
    __shared__ int w0sum;
    if (t == 31) w0sum = s;
    __syncthreads();
    if (t >= 32) s += w0sum;
    if (t < SCAN_B) g_part[t] = s - v;      // exclusive
}

// Phase 3: block-local exclusive scan + add block base; also zero g_cur
__global__ __launch_bounds__(SCAN_T) void scan3_kernel() {
    __shared__ int wsum[32];
    int i = blockIdx.x * SCAN_T + threadIdx.x;
    int v = (i < N_NODES) ? g_deg[i] : 0;
    int s = v;
#pragma unroll
    for (int o = 1; o < 32; o <<= 1) {
        int u = __shfl_up_sync(0xffffffffu, s, o);
        if ((threadIdx.x & 31) >= o) s += u;
    }
    if ((threadIdx.x & 31) == 31) wsum[threadIdx.x >> 5] = s;
    __syncthreads();
    if (threadIdx.x < 32) {
        int t = wsum[threadIdx.x];
#pragma unroll
        for (int o = 1; o < 32; o <<= 1) {
            int u = __shfl_up_sync(0xffffffffu, t, o);
            if (threadIdx.x >= o) t += u;
        }
        wsum[threadIdx.x] = t;
    }
    __syncthreads();
    int warp = threadIdx.x >> 5;
    int base = g_part[blockIdx.x] + (warp ? wsum[warp - 1] : 0);
    int excl = base + s - v;
    if (i < N_NODES) {
        g_off[i] = excl;
        g_cur[i] = 0;
        if (i == N_NODES - 1) g_off[N_NODES] = excl + v;
    }
}

__global__ void place_kernel(const void* __restrict__ eiv) {
    int e = blockIdx.x * blockDim.x + threadIdx.x;
    if (e < N_EDGES) {
        int src = load_idx(eiv, e);
        int dst = load_idx(eiv, N_EDGES + e);
        int pos = g_off[dst] + atomicAdd(&g_cur[dst], 1);
        if (pos >= 0 && pos < N_EDGES) g_src[pos] = src;
    }
}

// ---------------------------------------------------------------------------
// Gather mean aggregation: one warp per node, 3 coalesced columns per lane.
// ---------------------------------------------------------------------------
__global__ __launch_bounds__(256) void gather_kernel(const float* __restrict__ x,
                                                     int from_h) {
    int warp = (blockIdx.x * blockDim.x + threadIdx.x) >> 5;
    int lane = threadIdx.x & 31;
    if (warp >= N_NODES) return;
    const float* feat = from_h ? (const float*)g_h : x;
    int beg = g_off[warp];
    int end = g_off[warp + 1];
    float a0 = 0.f, a1 = 0.f, a2 = 0.f;
    int i = beg;
    for (; i + 1 < end; i += 2) {
        int s0 = g_src[i];
        int s1 = g_src[i + 1];
        const float* r0 = feat + (size_t)s0 * D;
        const float* r1 = feat + (size_t)s1 * D;
        float x0 = r0[lane], x1 = r0[lane + 32], x2 = r0[lane + 64];
        float y0 = r1[lane], y1 = r1[lane + 32], y2 = r1[lane + 64];
        a0 += x0 + y0; a1 += x1 + y1; a2 += x2 + y2;
    }
    if (i < end) {
        const float* r = feat + (size_t)g_src[i] * D;
        a0 += r[lane]; a1 += r[lane + 32]; a2 += r[lane + 64];
    }
    float inv = 1.0f / (float)max(end - beg, 1);
    float* o = g_agg + (size_t)warp * D;
    o[lane]      = a0 * inv;
    o[lane + 32] = a1 * inv;
    o[lane + 64] = a2 * inv;
}

// ---------------------------------------------------------------------------
// Fused SAGE linear layer with packed f32x2 FMA:
//   out[n] = g_agg[n] @ Wl^T + bias + feat[n] @ Wr^T   (optional ELU)
// One thread per node; 48 packed f32x2 accumulators; weights staged transposed
// in static shared (restaged between Wl and Wr phases; broadcast LDS.64 reads).
// ---------------------------------------------------------------------------
__global__ __launch_bounds__(128) void gemm_kernel(
    const float* __restrict__ x, int in_h,
    const float* __restrict__ Wl,
    const float* __restrict__ Wr,
    const float* __restrict__ bias,
    float* __restrict__ out, int out_h,
    int apply_elu)
{
    __shared__ __align__(16) float ws[D * WS];   // ws[k*WS + o] = W[o][k]
    __shared__ float bsm[D];

    const float* feat = in_h ? (const float*)g_h : x;
    float* dst = out_h ? (float*)g_h : out;

    for (int i = threadIdx.x; i < D * D; i += 128) {
        int o = i / D, k = i % D;
        ws[k * WS + o] = Wl[i];
    }
    if (threadIdx.x < D) bsm[threadIdx.x] = bias[threadIdx.x];
    __syncthreads();

    int node = blockIdx.x * 128 + threadIdx.x;
    bool active = node < N_NODES;

    u64 acc[48];
#pragma unroll
    for (int j = 0; j < 48; j++) acc[j] = pack2(bsm[2 * j], bsm[2 * j + 1]);

    const float4* a4 = (const float4*)(g_agg + (size_t)node * D);
    const float4* f4 = (const float4*)(feat + (size_t)node * D);

    if (active) {
#pragma unroll 1
        for (int kb = 0; kb < D / 4; kb++) {
            float4 av = a4[kb];
            const u64* w0 = (const u64*)(ws + (4 * kb + 0) * WS);
            const u64* w1 = (const u64*)(ws + (4 * kb + 1) * WS);
            const u64* w2 = (const u64*)(ws + (4 * kb + 2) * WS);
            const u64* w3 = (const u64*)(ws + (4 * kb + 3) * WS);
            u64 ax = pack2(av.x, av.x);
            u64 ay = pack2(av.y, av.y);
            u64 az = pack2(av.z, av.z);
            u64 aw = pack2(av.w, av.w);
#pragma unroll
            for (int j = 0; j < 48; j++) fma2(acc[j], ax, w0[j]);
#pragma unroll
            for (int j = 0; j < 48; j++) fma2(acc[j], ay, w1[j]);
#pragma unroll
            for (int j = 0; j < 48; j++) fma2(acc[j], az, w2[j]);
#pragma unroll
            for (int j = 0; j < 48; j++) fma2(acc[j], aw, w3[j]);
        }
    }

    __syncthreads();
    for (int i = threadIdx.x; i < D * D; i += 128) {
        int o = i / D, k = i % D;
        ws[k * WS + o] = Wr[i];
    }
    __syncthreads();

    if (active) {
#pragma unroll 1
        for (int kb = 0; kb < D / 4; kb++) {
            float4 fv = f4[kb];
            const u64* w0 = (const u64*)(ws + (4 * kb + 0) * WS);
            const u64* w1 = (const u64*)(ws + (4 * kb + 1) * WS);
            const u64* w2 = (const u64*)(ws + (4 * kb + 2) * WS);
            const u64* w3 = (const u64*)(ws + (4 * kb + 3) * WS);
            u64 ax = pack2(fv.x, fv.x);
            u64 ay = pack2(fv.y, fv.y);
            u64 az = pack2(fv.z, fv.z);
            u64 aw = pack2(fv.w, fv.w);
#pragma unroll
            for (int j = 0; j < 48; j++) fma2(acc[j], ax, w0[j]);
#pragma unroll
            for (int j = 0; j < 48; j++) fma2(acc[j], ay, w1[j]);
#pragma unroll
            for (int j = 0; j < 48; j++) fma2(acc[j], az, w2[j]);
#pragma unroll
            for (int j = 0; j < 48; j++) fma2(acc[j], aw, w3[j]);
        }

        float* o = dst + (size_t)node * D;
#pragma unroll
        for (int j = 0; j < 48; j++) {
            float lo, hi;
            unpack2(acc[j], lo, hi);
            if (apply_elu) {
                lo = lo > 0.0f ? lo : expm1f(lo);
                hi = hi > 0.0f ? hi : expm1f(hi);
            }
            o[2 * j]     = lo;
            o[2 * j + 1] = hi;
        }
    }
}

// ---------------------------------------------------------------------------
// Launch sequence (graph-capturable; kernel launches only).
// ---------------------------------------------------------------------------
extern "C" void kernel_launch(void* const* d_in, const int* in_sizes, int n_in,
                              void* d_out, int out_size) {
    const float* x   = (const float*)d_in[0];
    const void*  ei  = d_in[1];
    const float* W1l = (const float*)d_in[2];
    const float* b1  = (const float*)d_in[3];
    const float* W1r = (const float*)d_in[4];
    const float* W2l = (const float*)d_in[5];
    const float* b2  = (const float*)d_in[6];
    const float* W2r = (const float*)d_in[7];
    float*       out = (float*)d_out;

    const int nb = (N_NODES + 255) / 256;
    const int eb = (N_EDGES + 255) / 256;
    const int wb = (N_NODES * 32 + 255) / 256;
    const int gb = (N_NODES + 127) / 128;

    // CSR build (shared by both layers)
    detect_kernel<<<1, 64>>>((const int*)ei);
    zero_deg_kernel<<<nb, 256>>>();
    hist_kernel<<<eb, 256>>>(ei);
    scan1_kernel<<<SCAN_B, SCAN_T>>>();
    scan2_kernel<<<1, 64>>>();
    scan3_kernel<<<SCAN_B, SCAN_T>>>();
    place_kernel<<<eb, 256>>>(ei);

    // Layer 1: gather from x, gemm -> g_h (with ELU)
    gather_kernel<<<wb, 256>>>(x, 0);
    gemm_kernel<<<gb, 128>>>(x, 0, W1l, W1r, b1, nullptr, 1, 1);

    // Layer 2: gather from g_h, gemm -> out
    gather_kernel<<<wb, 256>>>(nullptr, 1);
    gemm_kernel<<<gb, 128>>>(nullptr, 1, W2l, W2r, b2, out, 0, 0);
}

// round 6
// speedup vs baseline: 1.5392x; 1.1743x over previous
#include <cuda_runtime.h>

#define N_NODES 50000
#define N_EDGES 800000
#define D 96
#define WS 100                  // padded weight stride: 400B rows, 16B-aligned
#define SCAN_T 1024
#define SCAN_B ((N_NODES + SCAN_T - 1) / SCAN_T)   // 49

typedef unsigned long long u64;

__device__ __align__(16) float g_agg[N_NODES * D];   // gathered mean features
__device__ __align__(16) float g_h[N_NODES * D];     // layer-1 activations
__device__ int g_deg[N_NODES];
__device__ int g_off[N_NODES + 1];
__device__ int g_cur[N_NODES];
__device__ int g_src[N_EDGES];                        // CSR: src ids grouped by dst
__device__ int g_part[SCAN_B];                        // per-block partial sums
__device__ int g_is64;                                // 1 if edge_index is int64

__device__ __forceinline__ u64 pack2(float lo, float hi) {
    u64 r; asm("mov.b64 %0, {%1, %2};" : "=l"(r) : "f"(lo), "f"(hi)); return r;
}
__device__ __forceinline__ void unpack2(u64 v, float& lo, float& hi) {
    asm("mov.b64 {%0, %1}, %2;" : "=f"(lo), "=f"(hi) : "l"(v));
}
__device__ __forceinline__ void fma2(u64& d, u64 a, u64 b) {
    asm("fma.rn.f32x2 %0, %1, %2, %0;" : "+l"(d) : "l"(a), "l"(b));
}

// ---------------------------------------------------------------------------
// Zero degrees; block 0 additionally detects edge_index element width.
// int64 small non-negative ids => all odd 32-bit words are zero.
// ---------------------------------------------------------------------------
__global__ void zero_detect_kernel(const int* __restrict__ w) {
    int i = blockIdx.x * blockDim.x + threadIdx.x;
    if (i < N_NODES) g_deg[i] = 0;
    if (blockIdx.x == 0 && threadIdx.x < 64) {
        int t = threadIdx.x;
        int bad = (w[2 * t + 1] != 0) ? 1 : 0;
        unsigned m0 = __ballot_sync(0xffffffffu, bad);
        __shared__ unsigned s[2];
        s[t >> 5] = m0;
        __syncwarp();
        if (t == 0) {
            __threadfence_block();
            g_is64 = (s[0] | s[1]) ? 0 : 1;
        }
    }
}

__device__ __forceinline__ int load_idx(const void* eiv, int pos) {
    int v;
    if (g_is64) v = (int)((const long long*)eiv)[pos];
    else        v = ((const int*)eiv)[pos];
    return min(max(v, 0), N_NODES - 1);     // safety clamp (no-op when correct)
}

__global__ void hist_kernel(const void* __restrict__ eiv) {
    int e = blockIdx.x * blockDim.x + threadIdx.x;
    if (e < N_EDGES) atomicAdd(&g_deg[load_idx(eiv, N_EDGES + e)], 1);
}

// Phase 1: per-block sums of degree chunks
__global__ __launch_bounds__(SCAN_T) void scan1_kernel() {
    __shared__ int wsum[32];
    int i = blockIdx.x * SCAN_T + threadIdx.x;
    int v = (i < N_NODES) ? g_deg[i] : 0;
    int s = v;
#pragma unroll
    for (int o = 1; o < 32; o <<= 1) s += __shfl_xor_sync(0xffffffffu, s, o);
    if ((threadIdx.x & 31) == 0) wsum[threadIdx.x >> 5] = s;
    __syncthreads();
    if (threadIdx.x < 32) {
        int t = wsum[threadIdx.x];
#pragma unroll
        for (int o = 1; o < 32; o <<= 1) t += __shfl_xor_sync(0xffffffffu, t, o);
        if (threadIdx.x == 0) g_part[blockIdx.x] = t;
    }
}

// Phase 2+3 fused: every block redundantly scans the 49 partials (cheap),
// then does its block-local exclusive scan + add base; zeroes g_cur.
__global__ __launch_bounds__(SCAN_T) void scan3_kernel() {
    __shared__ int wsum[32];
    __shared__ int base_excl[SCAN_B];

    // redundant exclusive scan of the 49 partials in the first 64 threads
    if (threadIdx.x < 64) {
        int t = threadIdx.x;
        int v = (t < SCAN_B) ? g_part[t] : 0;
        int s = v;
#pragma unroll
        for (int o = 1; o < 32; o <<= 1) {
            int u = __shfl_up_sync(0xffffffffu, s, o);
            if ((t & 31) >= o) s += u;
        }
        __shared__ int w0sum;
        if (t == 31) w0sum = s;
        __syncwarp();
        if (t >= 32) s += w0sum;
        if (t < SCAN_B) base_excl[t] = s - v;
    }
    __syncthreads();

    int i = blockIdx.x * SCAN_T + threadIdx.x;
    int v = (i < N_NODES) ? g_deg[i] : 0;
    int s = v;
#pragma unroll
    for (int o = 1; o < 32; o <<= 1) {
        int u = __shfl_up_sync(0xffffffffu, s, o);
        if ((threadIdx.x & 31) >= o) s += u;
    }
    if ((threadIdx.x & 31) == 31) wsum[threadIdx.x >> 5] = s;
    __syncthreads();
    if (threadIdx.x < 32) {
        int t = wsum[threadIdx.x];
#pragma unroll
        for (int o = 1; o < 32; o <<= 1) {
            int u = __shfl_up_sync(0xffffffffu, t, o);
            if (threadIdx.x >= o) t += u;
        }
        wsum[threadIdx.x] = t;
    }
    __syncthreads();
    int warp = threadIdx.x >> 5;
    int base = base_excl[blockIdx.x] + (warp ? wsum[warp - 1] : 0);
    int excl = base + s - v;
    if (i < N_NODES) {
        g_off[i] = excl;
        g_cur[i] = 0;
        if (i == N_NODES - 1) g_off[N_NODES] = excl + v;
    }
}

__global__ void place_kernel(const void* __restrict__ eiv) {
    int e = blockIdx.x * blockDim.x + threadIdx.x;
    if (e < N_EDGES) {
        int src = load_idx(eiv, e);
        int dst = load_idx(eiv, N_EDGES + e);
        int pos = g_off[dst] + atomicAdd(&g_cur[dst], 1);
        if (pos >= 0 && pos < N_EDGES) g_src[pos] = src;
    }
}

// ---------------------------------------------------------------------------
// Gather mean aggregation: one warp per node, 3 coalesced columns per lane,
// 4-edge unroll (12 outstanding loads) to hide L2 latency.
// ---------------------------------------------------------------------------
__global__ __launch_bounds__(256) void gather_kernel(const float* __restrict__ x,
                                                     int from_h) {
    int warp = (blockIdx.x * blockDim.x + threadIdx.x) >> 5;
    int lane = threadIdx.x & 31;
    if (warp >= N_NODES) return;
    const float* feat = from_h ? (const float*)g_h : x;
    int beg = g_off[warp];
    int end = g_off[warp + 1];
    float a0 = 0.f, a1 = 0.f, a2 = 0.f;
    int i = beg;
    for (; i + 3 < end; i += 4) {
        const float* r0 = feat + (size_t)g_src[i]     * D;
        const float* r1 = feat + (size_t)g_src[i + 1] * D;
        const float* r2 = feat + (size_t)g_src[i + 2] * D;
        const float* r3 = feat + (size_t)g_src[i + 3] * D;
        float p0 = r0[lane], p1 = r0[lane + 32], p2 = r0[lane + 64];
        float q0 = r1[lane], q1 = r1[lane + 32], q2 = r1[lane + 64];
        float s0 = r2[lane], s1 = r2[lane + 32], s2 = r2[lane + 64];
        float t0 = r3[lane], t1 = r3[lane + 32], t2 = r3[lane + 64];
        a0 += (p0 + q0) + (s0 + t0);
        a1 += (p1 + q1) + (s1 + t1);
        a2 += (p2 + q2) + (s2 + t2);
    }
    for (; i < end; i++) {
        const float* r = feat + (size_t)g_src[i] * D;
        a0 += r[lane]; a1 += r[lane + 32]; a2 += r[lane + 64];
    }
    float inv = 1.0f / (float)max(end - beg, 1);
    float* o = g_agg + (size_t)warp * D;
    o[lane]      = a0 * inv;
    o[lane + 32] = a1 * inv;
    o[lane + 64] = a2 * inv;
}

// ---------------------------------------------------------------------------
// Fused SAGE linear layer, packed f32x2 FMA + LDS.128 weight reads:
//   out[n] = g_agg[n] @ Wl^T + bias + feat[n] @ Wr^T   (optional ELU)
// ---------------------------------------------------------------------------
__global__ __launch_bounds__(128) void gemm_kernel(
    const float* __restrict__ x, int in_h,
    const float* __restrict__ Wl,
    const float* __restrict__ Wr,
    const float* __restrict__ bias,
    float* __restrict__ out, int out_h,
    int apply_elu)
{
    __shared__ __align__(16) float ws[D * WS];   // ws[k*WS + o] = W[o][k]
    __shared__ float bsm[D];

    const float* feat = in_h ? (const float*)g_h : x;
    float* dst = out_h ? (float*)g_h : out;

    for (int i = threadIdx.x; i < D * D; i += 128) {
        int o = i / D, k = i % D;
        ws[k * WS + o] = Wl[i];
    }
    if (threadIdx.x < D) bsm[threadIdx.x] = bias[threadIdx.x];
    __syncthreads();

    int node = blockIdx.x * 128 + threadIdx.x;
    bool active = node < N_NODES;

    u64 acc[48];
#pragma unroll
    for (int j = 0; j < 48; j++) acc[j] = pack2(bsm[2 * j], bsm[2 * j + 1]);

    const float4* a4 = (const float4*)(g_agg + (size_t)node * D);
    const float4* f4 = (const float4*)(feat + (size_t)node * D);

    if (active) {
#pragma unroll 1
        for (int kb = 0; kb < D / 4; kb++) {
            float4 av = a4[kb];
            const ulonglong2* w0 = (const ulonglong2*)(ws + (4 * kb + 0) * WS);
            const ulonglong2* w1 = (const ulonglong2*)(ws + (4 * kb + 1) * WS);
            const ulonglong2* w2 = (const ulonglong2*)(ws + (4 * kb + 2) * WS);
            const ulonglong2* w3 = (const ulonglong2*)(ws + (4 * kb + 3) * WS);
            u64 ax = pack2(av.x, av.x);
            u64 ay = pack2(av.y, av.y);
            u64 az = pack2(av.z, av.z);
            u64 aw = pack2(av.w, av.w);
#pragma unroll
            for (int j = 0; j < 24; j++) {
                ulonglong2 w = w0[j];
                fma2(acc[2 * j],     ax, w.x);
                fma2(acc[2 * j + 1], ax, w.y);
            }
#pragma unroll
            for (int j = 0; j < 24; j++) {
                ulonglong2 w = w1[j];
                fma2(acc[2 * j],     ay, w.x);
                fma2(acc[2 * j + 1], ay, w.y);
            }
#pragma unroll
            for (int j = 0; j < 24; j++) {
                ulonglong2 w = w2[j];
                fma2(acc[2 * j],     az, w.x);
                fma2(acc[2 * j + 1], az, w.y);
            }
#pragma unroll
            for (int j = 0; j < 24; j++) {
                ulonglong2 w = w3[j];
                fma2(acc[2 * j],     aw, w.x);
                fma2(acc[2 * j + 1], aw, w.y);
            }
        }
    }

    __syncthreads();
    for (int i = threadIdx.x; i < D * D; i += 128) {
        int o = i / D, k = i % D;
        ws[k * WS + o] = Wr[i];
    }
    __syncthreads();

    if (active) {
#pragma unroll 1
        for (int kb = 0; kb < D / 4; kb++) {
            float4 fv = f4[kb];
            const ulonglong2* w0 = (const ulonglong2*)(ws + (4 * kb + 0) * WS);
            const ulonglong2* w1 = (const ulonglong2*)(ws + (4 * kb + 1) * WS);
            const ulonglong2* w2 = (const ulonglong2*)(ws + (4 * kb + 2) * WS);
            const ulonglong2* w3 = (const ulonglong2*)(ws + (4 * kb + 3) * WS);
            u64 ax = pack2(fv.x, fv.x);
            u64 ay = pack2(fv.y, fv.y);
            u64 az = pack2(fv.z, fv.z);
            u64 aw = pack2(fv.w, fv.w);
#pragma unroll
            for (int j = 0; j < 24; j++) {
                ulonglong2 w = w0[j];
                fma2(acc[2 * j],     ax, w.x);
                fma2(acc[2 * j + 1], ax, w.y);
            }
#pragma unroll
            for (int j = 0; j < 24; j++) {
                ulonglong2 w = w1[j];
                fma2(acc[2 * j],     ay, w.x);
                fma2(acc[2 * j + 1], ay, w.y);
            }
#pragma unroll
            for (int j = 0; j < 24; j++) {
                ulonglong2 w = w2[j];
                fma2(acc[2 * j],     az, w.x);
                fma2(acc[2 * j + 1], az, w.y);
            }
#pragma unroll
            for (int j = 0; j < 24; j++) {
                ulonglong2 w = w3[j];
                fma2(acc[2 * j],     aw, w.x);
                fma2(acc[2 * j + 1], aw, w.y);
            }
        }

        float* o = dst + (size_t)node * D;
#pragma unroll
        for (int j = 0; j < 48; j++) {
            float lo, hi;
            unpack2(acc[j], lo, hi);
            if (apply_elu) {
                lo = lo > 0.0f ? lo : expm1f(lo);
                hi = hi > 0.0f ? hi : expm1f(hi);
            }
            o[2 * j]     = lo;
            o[2 * j + 1] = hi;
        }
    }
}

// ---------------------------------------------------------------------------
// Launch sequence (graph-capturable; kernel launches only).
// ---------------------------------------------------------------------------
extern "C" void kernel_launch(void* const* d_in, const int* in_sizes, int n_in,
                              void* d_out, int out_size) {
    const float* x   = (const float*)d_in[0];
    const void*  ei  = d_in[1];
    const float* W1l = (const float*)d_in[2];
    const float* b1  = (const float*)d_in[3];
    const float* W1r = (const float*)d_in[4];
    const float* W2l = (const float*)d_in[5];
    const float* b2  = (const float*)d_in[6];
    const float* W2r = (const float*)d_in[7];
    float*       out = (float*)d_out;

    const int nb = (N_NODES + 255) / 256;
    const int eb = (N_EDGES + 255) / 256;
    const int wb = (N_NODES * 32 + 255) / 256;
    const int gb = (N_NODES + 127) / 128;

    // CSR build (shared by both layers)
    zero_detect_kernel<<<nb, 256>>>((const int*)ei);
    hist_kernel<<<eb, 256>>>(ei);
    scan1_kernel<<<SCAN_B, SCAN_T>>>();
    scan3_kernel<<<SCAN_B, SCAN_T>>>();
    place_kernel<<<eb, 256>>>(ei);

    // Layer 1: gather from x, gemm -> g_h (with ELU)
    gather_kernel<<<wb, 256>>>(x, 0);
    gemm_kernel<<<gb, 128>>>(x, 0, W1l, W1r, b1, nullptr, 1, 1);

    // Layer 2: gather from g_h, gemm -> out
    gather_kernel<<<wb, 256>>>(nullptr, 1);
    gemm_kernel<<<gb, 128>>>(nullptr, 1, W2l, W2r, b2, out, 0, 0);
}